// round 2
// baseline (speedup 1.0000x reference)
#include <cuda_runtime.h>
#include <cuda_bf16.h>

#define NN 50000
#define EEDGE 500000
#define GG 64
#define HH 2
#define DDIM 64
#define FF 128          // H*D
#define CC 5
#define SLOPE 0.2f
#define ENC_NEG_INF 0x007FFFFFu

// ---------------- scratch (device globals; no allocation allowed) ------------
__device__ float    g_h[NN * FF];      // h = x @ W  (pre-aggregation features)
__device__ float    g_out[NN * FF];    // aggregated messages
__device__ float    g_x[NN * FF];      // layer output / next layer input
__device__ float    g_as[NN * HH];     // alpha_src per node
__device__ float    g_ad[NN * HH];     // alpha_dst per node
__device__ unsigned g_max[NN * HH];    // segment max (encoded float)
__device__ float    g_den[NN * HH];    // softmax denominator
__device__ float    g_ee[EEDGE * HH];  // per-edge scores -> exp values
__device__ float    g_pool[GG * FF];
__device__ float    g_cnt[GG];

// ---------------- helpers ----------------------------------------------------
__device__ __forceinline__ unsigned enc_f(float f) {
    unsigned u = __float_as_uint(f);
    return (u & 0x80000000u) ? ~u : (u | 0x80000000u);
}
__device__ __forceinline__ float dec_f(unsigned u) {
    return __uint_as_float((u & 0x80000000u) ? (u & 0x7FFFFFFFu) : ~u);
}

// ---------------- kernels ----------------------------------------------------

// Layer 1 GEMM: [N,4] x [4,128]
__global__ void gemm1_k(const float* __restrict__ x, const float* __restrict__ W,
                        float* __restrict__ h) {
    __shared__ float Ws[4 * FF];
    int tid = threadIdx.x;
    if (tid < 4 * FF) Ws[tid] = W[tid];
    __syncthreads();
    int i = blockIdx.x * blockDim.x + tid;
    if (i >= NN * FF) return;
    int n = i >> 7, c = i & 127;
    const float* xr = x + n * 4;
    float acc = xr[0] * Ws[c] + xr[1] * Ws[FF + c] + xr[2] * Ws[2 * FF + c] + xr[3] * Ws[3 * FF + c];
    h[i] = acc;
}

// Layers 2-4 GEMM: [N,128] x [128,128], 32-row tiles, 4x4 register blocking
__global__ void gemm128_k(const float* __restrict__ x, const float* __restrict__ W,
                          float* __restrict__ h) {
    extern __shared__ float sm[];
    float* Ws = sm;               // 128*128
    float* Xs = sm + FF * FF;     // 32*128
    int tid = threadIdx.x;
    for (int i = tid; i < FF * FF; i += 256) Ws[i] = W[i];
    int row0 = blockIdx.x * 32;
    for (int i = tid; i < 32 * FF; i += 256) {
        int r = row0 + (i >> 7);
        Xs[i] = (r < NN) ? x[r * FF + (i & 127)] : 0.f;
    }
    __syncthreads();
    int c  = tid & 31;
    int rb = (tid >> 5) * 4;
    float acc[4][4] = {};
#pragma unroll 8
    for (int k = 0; k < FF; k++) {
        float w0 = Ws[k * FF + c];
        float w1 = Ws[k * FF + c + 32];
        float w2 = Ws[k * FF + c + 64];
        float w3 = Ws[k * FF + c + 96];
#pragma unroll
        for (int r = 0; r < 4; r++) {
            float xv = Xs[(rb + r) * FF + k];
            acc[r][0] += xv * w0; acc[r][1] += xv * w1;
            acc[r][2] += xv * w2; acc[r][3] += xv * w3;
        }
    }
#pragma unroll
    for (int r = 0; r < 4; r++) {
        int row = row0 + rb + r;
        if (row < NN) {
            float* hp = h + row * FF;
            hp[c] = acc[r][0]; hp[c + 32] = acc[r][1];
            hp[c + 64] = acc[r][2]; hp[c + 96] = acc[r][3];
        }
    }
}

// Per-node attention coefficients: alpha_src/dst[n,h] = sum_d h[n,h,d]*a[h,d]
__global__ void alpha_k(const float* __restrict__ h, const float* __restrict__ asrc,
                        const float* __restrict__ adst,
                        float* __restrict__ as_, float* __restrict__ ad_) {
    int n = (blockIdx.x * blockDim.x + threadIdx.x) >> 5;
    int lane = threadIdx.x & 31;
    if (n >= NN) return;
    const float* hr = h + n * FF;
    float v0 = hr[lane],      v1 = hr[lane + 32];
    float v2 = hr[lane + 64], v3 = hr[lane + 96];
    float s0 = v0 * asrc[lane] + v1 * asrc[lane + 32];
    float d0 = v0 * adst[lane] + v1 * adst[lane + 32];
    float s1 = v2 * asrc[64 + lane] + v3 * asrc[96 + lane];
    float d1 = v2 * adst[64 + lane] + v3 * adst[96 + lane];
#pragma unroll
    for (int o = 16; o; o >>= 1) {
        s0 += __shfl_xor_sync(0xffffffffu, s0, o);
        d0 += __shfl_xor_sync(0xffffffffu, d0, o);
        s1 += __shfl_xor_sync(0xffffffffu, s1, o);
        d1 += __shfl_xor_sync(0xffffffffu, d1, o);
    }
    if (lane == 0) {
        as_[n * 2] = s0; as_[n * 2 + 1] = s1;
        ad_[n * 2] = d0; ad_[n * 2 + 1] = d1;
    }
}

// Reset per-layer accumulators
__global__ void init_k(unsigned* __restrict__ nmax, float* __restrict__ den,
                       float* __restrict__ outb) {
    int i = blockIdx.x * blockDim.x + threadIdx.x;
    if (i < NN * HH) { nmax[i] = ENC_NEG_INF; den[i] = 0.f; }
    if (i < NN * FF) outb[i] = 0.f;
}

// Pass A: edge score + segment max
__global__ void passA_k(const int* __restrict__ srcv, const int* __restrict__ dstv,
                        const float* __restrict__ as_, const float* __restrict__ ad_,
                        float* __restrict__ ee, unsigned* __restrict__ nmax) {
    int e = blockIdx.x * blockDim.x + threadIdx.x;
    if (e >= EEDGE) return;
    int s = srcv[e], d = dstv[e];
    float e0 = as_[s * 2] + ad_[d * 2];
    float e1 = as_[s * 2 + 1] + ad_[d * 2 + 1];
    e0 = e0 > 0.f ? e0 : SLOPE * e0;
    e1 = e1 > 0.f ? e1 : SLOPE * e1;
    reinterpret_cast<float2*>(ee)[e] = make_float2(e0, e1);
    atomicMax(&nmax[d * 2], enc_f(e0));
    atomicMax(&nmax[d * 2 + 1], enc_f(e1));
}

// Pass B: exp(e - max) + denominator
__global__ void passB_k(const int* __restrict__ dstv, float* __restrict__ ee,
                        const unsigned* __restrict__ nmax, float* __restrict__ den) {
    int e = blockIdx.x * blockDim.x + threadIdx.x;
    if (e >= EEDGE) return;
    int d = dstv[e];
    float2 ev = reinterpret_cast<float2*>(ee)[e];
    float v0 = expf(ev.x - dec_f(nmax[d * 2]));
    float v1 = expf(ev.y - dec_f(nmax[d * 2 + 1]));
    reinterpret_cast<float2*>(ee)[e] = make_float2(v0, v1);
    atomicAdd(&den[d * 2], v0);
    atomicAdd(&den[d * 2 + 1], v1);
}

// Pass C: gather h[src], scale by alpha, scatter-add to out[dst]. Warp per edge.
__global__ void passC_k(const int* __restrict__ srcv, const int* __restrict__ dstv,
                        const float* __restrict__ ee, const float* __restrict__ den,
                        const float* __restrict__ h, float* __restrict__ outb) {
    int e = (blockIdx.x * blockDim.x + threadIdx.x) >> 5;
    int lane = threadIdx.x & 31;
    if (e >= EEDGE) return;
    int s = srcv[e], d = dstv[e];
    float2 ev = reinterpret_cast<const float2*>(ee)[e];
    float a0 = ev.x / (den[d * 2] + 1e-16f);
    float a1 = ev.y / (den[d * 2 + 1] + 1e-16f);
    float a = (lane < 16) ? a0 : a1;
    float4 v = reinterpret_cast<const float4*>(h + s * FF)[lane];
    float* p = outb + d * FF + lane * 4;
    atomicAdd(p,     v.x * a);
    atomicAdd(p + 1, v.y * a);
    atomicAdd(p + 2, v.z * a);
    atomicAdd(p + 3, v.w * a);
}

// Bias + ReLU -> next layer input
__global__ void finish_k(const float* __restrict__ outb, const float* __restrict__ b,
                         float* __restrict__ xn) {
    int i = blockIdx.x * blockDim.x + threadIdx.x;
    if (i >= NN * FF) return;
    xn[i] = fmaxf(outb[i] + b[i & 127], 0.f);
}

__global__ void poolinit_k(float* __restrict__ pooled, float* __restrict__ cnt) {
    int i = blockIdx.x * blockDim.x + threadIdx.x;
    if (i < GG * FF) pooled[i] = 0.f;
    if (i < GG) cnt[i] = 0.f;
}

// Mean-pool accumulation. Warp per node.
__global__ void pool_k(const int* __restrict__ batch, const float* __restrict__ x,
                       float* __restrict__ pooled, float* __restrict__ cnt) {
    int n = (blockIdx.x * blockDim.x + threadIdx.x) >> 5;
    int lane = threadIdx.x & 31;
    if (n >= NN) return;
    int g = batch[n];
    float4 v = reinterpret_cast<const float4*>(x + n * FF)[lane];
    float* p = pooled + g * FF + lane * 4;
    atomicAdd(p,     v.x);
    atomicAdd(p + 1, v.y);
    atomicAdd(p + 2, v.z);
    atomicAdd(p + 3, v.w);
    if (lane == 0) atomicAdd(&cnt[g], 1.f);
}

// Final: mean, linear [128->5], sigmoid
__global__ void final_k(const float* __restrict__ pooled, const float* __restrict__ cnt,
                        const float* __restrict__ lw, const float* __restrict__ lb,
                        float* __restrict__ out) {
    int t = threadIdx.x;
    if (t >= GG * CC) return;
    int g = t / CC, c = t % CC;
    float inv = 1.f / fmaxf(cnt[g], 1.f);
    float acc = lb[c];
    for (int k = 0; k < FF; k++)
        acc += pooled[g * FF + k] * inv * lw[k * CC + c];
    out[t] = 1.f / (1.f + expf(-acc));
}

// ---------------- launch ------------------------------------------------------
extern "C" void kernel_launch(void* const* d_in, const int* in_sizes, int n_in,
                              void* d_out, int out_size) {
    const float* x     = (const float*)d_in[0];
    const int*   ei    = (const int*)d_in[1];
    const int*   batch = (const int*)d_in[2];
    const float* W[4]    = {(const float*)d_in[3],  (const float*)d_in[7],
                            (const float*)d_in[11], (const float*)d_in[15]};
    const float* asrc[4] = {(const float*)d_in[4],  (const float*)d_in[8],
                            (const float*)d_in[12], (const float*)d_in[16]};
    const float* adst[4] = {(const float*)d_in[5],  (const float*)d_in[9],
                            (const float*)d_in[13], (const float*)d_in[17]};
    const float* bias[4] = {(const float*)d_in[6],  (const float*)d_in[10],
                            (const float*)d_in[14], (const float*)d_in[18]};
    const float* lin_w = (const float*)d_in[19];
    const float* lin_b = (const float*)d_in[20];
    float* out = (float*)d_out;

    const int* srcv = ei;
    const int* dstv = ei + EEDGE;

    void *ph, *pout, *px, *pas, *pad, *pmax, *pden, *pee, *ppool, *pcnt;
    cudaGetSymbolAddress(&ph,   g_h);
    cudaGetSymbolAddress(&pout, g_out);
    cudaGetSymbolAddress(&px,   g_x);
    cudaGetSymbolAddress(&pas,  g_as);
    cudaGetSymbolAddress(&pad,  g_ad);
    cudaGetSymbolAddress(&pmax, g_max);
    cudaGetSymbolAddress(&pden, g_den);
    cudaGetSymbolAddress(&pee,  g_ee);
    cudaGetSymbolAddress(&ppool,g_pool);
    cudaGetSymbolAddress(&pcnt, g_cnt);

    const int SMEM_GEMM = (FF * FF + 32 * FF) * sizeof(float);  // 80KB
    cudaFuncSetAttribute(gemm128_k, cudaFuncAttributeMaxDynamicSharedMemorySize, SMEM_GEMM);

    const int NF = NN * FF;
    dim3 b256(256);

    for (int l = 0; l < 4; l++) {
        // 1) GEMM
        if (l == 0) {
            gemm1_k<<<(NF + 511) / 512, 512>>>(x, W[0], (float*)ph);
        } else {
            gemm128_k<<<(NN + 31) / 32, 256, SMEM_GEMM>>>((const float*)px, W[l], (float*)ph);
        }
        // 2) per-node attention coefficients
        alpha_k<<<(NN + 7) / 8, 256>>>((const float*)ph, asrc[l], adst[l],
                                       (float*)pas, (float*)pad);
        // 3) reset accumulators
        init_k<<<(NF + 255) / 256, 256>>>((unsigned*)pmax, (float*)pden, (float*)pout);
        // 4) edge passes
        passA_k<<<(EEDGE + 255) / 256, 256>>>(srcv, dstv, (const float*)pas,
                                              (const float*)pad, (float*)pee, (unsigned*)pmax);
        passB_k<<<(EEDGE + 255) / 256, 256>>>(dstv, (float*)pee,
                                              (const unsigned*)pmax, (float*)pden);
        passC_k<<<(EEDGE * 32) / 256, 256>>>(srcv, dstv, (const float*)pee,
                                             (const float*)pden, (const float*)ph, (float*)pout);
        // 5) bias + relu
        finish_k<<<(NF + 255) / 256, 256>>>((const float*)pout, bias[l], (float*)px);
    }

    poolinit_k<<<(GG * FF + 255) / 256, 256>>>((float*)ppool, (float*)pcnt);
    pool_k<<<(NN * 32 + 255) / 256, 256>>>(batch, (const float*)px,
                                           (float*)ppool, (float*)pcnt);
    final_k<<<1, 512>>>((const float*)ppool, (const float*)pcnt, lin_w, lin_b, out);
}

// round 3
// speedup vs baseline: 1.9905x; 1.9905x over previous
#include <cuda_runtime.h>
#include <cuda_bf16.h>

#define NN 50000
#define EEDGE 500000
#define GG 64
#define HH 2
#define FF 128          // H*D
#define CC 5
#define SLOPE 0.2f

// ---------------- scratch (device globals; no allocation allowed) ------------
__device__ float g_h[NN * FF];       // h = x @ W  (pre-aggregation features)
__device__ float g_x[NN * FF];       // layer output / next layer input
__device__ float g_as[NN * HH];      // alpha_src per node
__device__ float g_ad[NN * HH];      // alpha_dst per node
__device__ float g_pool[GG * FF];
__device__ float g_cnt[GG];
// CSR (built once per launch)
__device__ int   g_deg[NN];
__device__ int   g_cursor[NN];
__device__ int   g_rowptr[NN + 1];
__device__ int   g_csrc[EEDGE];      // src node of each dst-grouped edge

// ---------------- CSR build ---------------------------------------------------
__global__ void zero_k(int* __restrict__ deg, int* __restrict__ cursor) {
    int i = blockIdx.x * blockDim.x + threadIdx.x;
    if (i < NN) { deg[i] = 0; cursor[i] = 0; }
}

__global__ void hist_k(const int* __restrict__ dstv, int* __restrict__ deg) {
    int e = blockIdx.x * blockDim.x + threadIdx.x;
    if (e < EEDGE) atomicAdd(&deg[dstv[e]], 1);
}

// single-block exclusive scan over 50001 entries
__global__ void scan_k(const int* __restrict__ deg, int* __restrict__ rowptr) {
    __shared__ int part[1024];
    const int CH = (NN + 1023) / 1024;  // 49
    int t = threadIdx.x;
    int base = t * CH;
    int s = 0;
    for (int i = 0; i < CH; i++) {
        int idx = base + i;
        if (idx < NN) s += deg[idx];
    }
    part[t] = s;
    __syncthreads();
    for (int off = 1; off < 1024; off <<= 1) {
        int v = (t >= off) ? part[t - off] : 0;
        __syncthreads();
        part[t] += v;
        __syncthreads();
    }
    int run = (t == 0) ? 0 : part[t - 1];
    for (int i = 0; i < CH; i++) {
        int idx = base + i;
        if (idx <= NN) {
            rowptr[idx] = run;
            if (idx < NN) run += deg[idx];
        }
    }
}

__global__ void scatter_k(const int* __restrict__ srcv, const int* __restrict__ dstv,
                          const int* __restrict__ rowptr, int* __restrict__ cursor,
                          int* __restrict__ csrc) {
    int e = blockIdx.x * blockDim.x + threadIdx.x;
    if (e >= EEDGE) return;
    int d = dstv[e];
    int pos = rowptr[d] + atomicAdd(&cursor[d], 1);
    csrc[pos] = srcv[e];
}

// ---------------- per-layer kernels -------------------------------------------

// Layer 1 GEMM: [N,4] x [4,128]
__global__ void gemm1_k(const float* __restrict__ x, const float* __restrict__ W,
                        float* __restrict__ h) {
    __shared__ float Ws[4 * FF];
    int tid = threadIdx.x;
    if (tid < 4 * FF) Ws[tid] = W[tid];
    __syncthreads();
    int i = blockIdx.x * blockDim.x + tid;
    if (i >= NN * FF) return;
    int n = i >> 7, c = i & 127;
    const float* xr = x + n * 4;
    h[i] = xr[0] * Ws[c] + xr[1] * Ws[FF + c] + xr[2] * Ws[2 * FF + c] + xr[3] * Ws[3 * FF + c];
}

// Layers 2-4 GEMM: [N,128] x [128,128], 32-row tiles, 4x4 register blocking
__global__ void gemm128_k(const float* __restrict__ x, const float* __restrict__ W,
                          float* __restrict__ h) {
    extern __shared__ float sm[];
    float* Ws = sm;               // 128*128
    float* Xs = sm + FF * FF;     // 32*128
    int tid = threadIdx.x;
    for (int i = tid; i < FF * FF; i += 256) Ws[i] = W[i];
    int row0 = blockIdx.x * 32;
    for (int i = tid; i < 32 * FF; i += 256) {
        int r = row0 + (i >> 7);
        Xs[i] = (r < NN) ? x[r * FF + (i & 127)] : 0.f;
    }
    __syncthreads();
    int c  = tid & 31;
    int rb = (tid >> 5) * 4;
    float acc[4][4] = {};
#pragma unroll 8
    for (int k = 0; k < FF; k++) {
        float w0 = Ws[k * FF + c];
        float w1 = Ws[k * FF + c + 32];
        float w2 = Ws[k * FF + c + 64];
        float w3 = Ws[k * FF + c + 96];
#pragma unroll
        for (int r = 0; r < 4; r++) {
            float xv = Xs[(rb + r) * FF + k];
            acc[r][0] += xv * w0; acc[r][1] += xv * w1;
            acc[r][2] += xv * w2; acc[r][3] += xv * w3;
        }
    }
#pragma unroll
    for (int r = 0; r < 4; r++) {
        int row = row0 + rb + r;
        if (row < NN) {
            float* hp = h + row * FF;
            hp[c] = acc[r][0]; hp[c + 32] = acc[r][1];
            hp[c + 64] = acc[r][2]; hp[c + 96] = acc[r][3];
        }
    }
}

// Per-node attention coefficients
__global__ void alpha_k(const float* __restrict__ h, const float* __restrict__ asrc,
                        const float* __restrict__ adst,
                        float* __restrict__ as_, float* __restrict__ ad_) {
    int n = (blockIdx.x * blockDim.x + threadIdx.x) >> 5;
    int lane = threadIdx.x & 31;
    if (n >= NN) return;
    const float* hr = h + n * FF;
    float v0 = hr[lane],      v1 = hr[lane + 32];
    float v2 = hr[lane + 64], v3 = hr[lane + 96];
    float s0 = v0 * asrc[lane] + v1 * asrc[lane + 32];
    float d0 = v0 * adst[lane] + v1 * adst[lane + 32];
    float s1 = v2 * asrc[64 + lane] + v3 * asrc[96 + lane];
    float d1 = v2 * adst[64 + lane] + v3 * adst[96 + lane];
#pragma unroll
    for (int o = 16; o; o >>= 1) {
        s0 += __shfl_xor_sync(0xffffffffu, s0, o);
        d0 += __shfl_xor_sync(0xffffffffu, d0, o);
        s1 += __shfl_xor_sync(0xffffffffu, s1, o);
        d1 += __shfl_xor_sync(0xffffffffu, d1, o);
    }
    if (lane == 0) {
        as_[n * 2] = s0; as_[n * 2 + 1] = s1;
        ad_[n * 2] = d0; ad_[n * 2 + 1] = d1;
    }
}

// Fused aggregation: softmax over incoming edges + weighted gather + bias + ReLU.
// One warp per dst node. No atomics.
__global__ void agg_k(const int* __restrict__ rowptr, const int* __restrict__ csrc,
                      const float* __restrict__ as_, const float* __restrict__ ad_,
                      const float* __restrict__ h, const float* __restrict__ b,
                      float* __restrict__ xo) {
    int n = (blockIdx.x * blockDim.x + threadIdx.x) >> 5;
    int lane = threadIdx.x & 31;
    if (n >= NN) return;
    int beg = rowptr[n], end = rowptr[n + 1];
    float ad0 = ad_[2 * n], ad1 = ad_[2 * n + 1];

    // pass 1: segment max (lane-parallel over edges)
    float m0 = -1e30f, m1 = -1e30f;
    for (int i = beg + lane; i < end; i += 32) {
        int s = csrc[i];
        float e0 = as_[2 * s] + ad0;     e0 = e0 > 0.f ? e0 : SLOPE * e0;
        float e1 = as_[2 * s + 1] + ad1; e1 = e1 > 0.f ? e1 : SLOPE * e1;
        m0 = fmaxf(m0, e0); m1 = fmaxf(m1, e1);
    }
#pragma unroll
    for (int o = 16; o; o >>= 1) {
        m0 = fmaxf(m0, __shfl_xor_sync(0xffffffffu, m0, o));
        m1 = fmaxf(m1, __shfl_xor_sync(0xffffffffu, m1, o));
    }

    // pass 2: denominator
    float s0 = 0.f, s1 = 0.f;
    for (int i = beg + lane; i < end; i += 32) {
        int s = csrc[i];
        float e0 = as_[2 * s] + ad0;     e0 = e0 > 0.f ? e0 : SLOPE * e0;
        float e1 = as_[2 * s + 1] + ad1; e1 = e1 > 0.f ? e1 : SLOPE * e1;
        s0 += __expf(e0 - m0); s1 += __expf(e1 - m1);
    }
#pragma unroll
    for (int o = 16; o; o >>= 1) {
        s0 += __shfl_xor_sync(0xffffffffu, s0, o);
        s1 += __shfl_xor_sync(0xffffffffu, s1, o);
    }
    float inv0 = 1.f / (s0 + 1e-16f);
    float inv1 = 1.f / (s1 + 1e-16f);

    // pass 3: weighted feature gather (whole warp per edge, sequential over edges)
    float4 acc = make_float4(0.f, 0.f, 0.f, 0.f);
    for (int i = beg; i < end; i++) {
        int s = csrc[i];                              // broadcast
        float e0 = as_[2 * s] + ad0;     e0 = e0 > 0.f ? e0 : SLOPE * e0;
        float e1 = as_[2 * s + 1] + ad1; e1 = e1 > 0.f ? e1 : SLOPE * e1;
        float p = (lane < 16) ? __expf(e0 - m0) * inv0 : __expf(e1 - m1) * inv1;
        float4 v = reinterpret_cast<const float4*>(h + (size_t)s * FF)[lane];
        acc.x += v.x * p; acc.y += v.y * p; acc.z += v.z * p; acc.w += v.w * p;
    }

    float4 bv = reinterpret_cast<const float4*>(b)[lane];
    float4 r;
    r.x = fmaxf(acc.x + bv.x, 0.f);
    r.y = fmaxf(acc.y + bv.y, 0.f);
    r.z = fmaxf(acc.z + bv.z, 0.f);
    r.w = fmaxf(acc.w + bv.w, 0.f);
    reinterpret_cast<float4*>(xo + (size_t)n * FF)[lane] = r;
}

// ---------------- pooling + classifier ----------------------------------------
__global__ void poolinit_k(float* __restrict__ pooled, float* __restrict__ cnt) {
    int i = blockIdx.x * blockDim.x + threadIdx.x;
    if (i < GG * FF) pooled[i] = 0.f;
    if (i < GG) cnt[i] = 0.f;
}

__global__ void pool_k(const int* __restrict__ batch, const float* __restrict__ x,
                       float* __restrict__ pooled, float* __restrict__ cnt) {
    int n = (blockIdx.x * blockDim.x + threadIdx.x) >> 5;
    int lane = threadIdx.x & 31;
    if (n >= NN) return;
    int g = batch[n];
    float4 v = reinterpret_cast<const float4*>(x + n * FF)[lane];
    float* p = pooled + g * FF + lane * 4;
    atomicAdd(p,     v.x);
    atomicAdd(p + 1, v.y);
    atomicAdd(p + 2, v.z);
    atomicAdd(p + 3, v.w);
    if (lane == 0) atomicAdd(&cnt[g], 1.f);
}

__global__ void final_k(const float* __restrict__ pooled, const float* __restrict__ cnt,
                        const float* __restrict__ lw, const float* __restrict__ lb,
                        float* __restrict__ out) {
    int t = threadIdx.x;
    if (t >= GG * CC) return;
    int g = t / CC, c = t % CC;
    float inv = 1.f / fmaxf(cnt[g], 1.f);
    float acc = lb[c];
    for (int k = 0; k < FF; k++)
        acc += pooled[g * FF + k] * inv * lw[k * CC + c];
    out[t] = 1.f / (1.f + expf(-acc));
}

// ---------------- launch ------------------------------------------------------
extern "C" void kernel_launch(void* const* d_in, const int* in_sizes, int n_in,
                              void* d_out, int out_size) {
    const float* x     = (const float*)d_in[0];
    const int*   ei    = (const int*)d_in[1];
    const int*   batch = (const int*)d_in[2];
    const float* W[4]    = {(const float*)d_in[3],  (const float*)d_in[7],
                            (const float*)d_in[11], (const float*)d_in[15]};
    const float* asrc[4] = {(const float*)d_in[4],  (const float*)d_in[8],
                            (const float*)d_in[12], (const float*)d_in[16]};
    const float* adst[4] = {(const float*)d_in[5],  (const float*)d_in[9],
                            (const float*)d_in[13], (const float*)d_in[17]};
    const float* bias[4] = {(const float*)d_in[6],  (const float*)d_in[10],
                            (const float*)d_in[14], (const float*)d_in[18]};
    const float* lin_w = (const float*)d_in[19];
    const float* lin_b = (const float*)d_in[20];
    float* out = (float*)d_out;

    const int* srcv = ei;
    const int* dstv = ei + EEDGE;

    void *ph, *px, *pas, *pad, *ppool, *pcnt, *pdeg, *pcur, *prp, *pcs;
    cudaGetSymbolAddress(&ph,   g_h);
    cudaGetSymbolAddress(&px,   g_x);
    cudaGetSymbolAddress(&pas,  g_as);
    cudaGetSymbolAddress(&pad,  g_ad);
    cudaGetSymbolAddress(&ppool,g_pool);
    cudaGetSymbolAddress(&pcnt, g_cnt);
    cudaGetSymbolAddress(&pdeg, g_deg);
    cudaGetSymbolAddress(&pcur, g_cursor);
    cudaGetSymbolAddress(&prp,  g_rowptr);
    cudaGetSymbolAddress(&pcs,  g_csrc);

    const int SMEM_GEMM = (FF * FF + 32 * FF) * sizeof(float);  // 80KB
    cudaFuncSetAttribute(gemm128_k, cudaFuncAttributeMaxDynamicSharedMemorySize, SMEM_GEMM);

    const int NF = NN * FF;

    // ---- CSR build (once; shared by all 4 layers) ----
    zero_k<<<(NN + 255) / 256, 256>>>((int*)pdeg, (int*)pcur);
    hist_k<<<(EEDGE + 255) / 256, 256>>>(dstv, (int*)pdeg);
    scan_k<<<1, 1024>>>((const int*)pdeg, (int*)prp);
    scatter_k<<<(EEDGE + 255) / 256, 256>>>(srcv, dstv, (const int*)prp,
                                            (int*)pcur, (int*)pcs);

    // ---- 4 GAT layers ----
    for (int l = 0; l < 4; l++) {
        if (l == 0) {
            gemm1_k<<<(NF + 511) / 512, 512>>>(x, W[0], (float*)ph);
        } else {
            gemm128_k<<<(NN + 31) / 32, 256, SMEM_GEMM>>>((const float*)px, W[l], (float*)ph);
        }
        alpha_k<<<(NN + 7) / 8, 256>>>((const float*)ph, asrc[l], adst[l],
                                       (float*)pas, (float*)pad);
        agg_k<<<(NN * 32 + 255) / 256, 256>>>((const int*)prp, (const int*)pcs,
                                              (const float*)pas, (const float*)pad,
                                              (const float*)ph, bias[l], (float*)px);
    }

    // ---- pooling + classifier ----
    poolinit_k<<<(GG * FF + 255) / 256, 256>>>((float*)ppool, (float*)pcnt);
    pool_k<<<(NN * 32 + 255) / 256, 256>>>(batch, (const float*)px,
                                           (float*)ppool, (float*)pcnt);
    final_k<<<1, 512>>>((const float*)ppool, (const float*)pcnt, lin_w, lin_b, out);
}

// round 4
// speedup vs baseline: 3.0172x; 1.5157x over previous
#include <cuda_runtime.h>
#include <cuda_bf16.h>

#define NN 50000
#define EEDGE 500000
#define GG 64
#define HH 2
#define FF 128          // H*D
#define CC 5
#define SLOPE 0.2f
#define SX 132          // padded bf16 row stride (128 + 4) -> <=2-way LDS conflicts

// ---------------- scratch (device globals; no allocation allowed) ------------
__device__ float g_h[NN * FF];       // h = x @ W  (pre-aggregation features)
__device__ float g_x[NN * FF];       // layer output / next layer input
__device__ float g_as[NN * HH];      // alpha_src per node
__device__ float g_ad[NN * HH];      // alpha_dst per node
__device__ float g_pool[GG * FF];
__device__ float g_cnt[GG];
// CSR (built once per launch)
__device__ int   g_deg[NN];
__device__ int   g_cursor[NN];
__device__ int   g_rowptr[NN + 1];
__device__ int   g_csrc[EEDGE];      // src node of each dst-grouped edge

// ---------------- CSR build ---------------------------------------------------
__global__ void zero_k(int* __restrict__ deg, int* __restrict__ cursor) {
    int i = blockIdx.x * blockDim.x + threadIdx.x;
    if (i < NN) { deg[i] = 0; cursor[i] = 0; }
}

__global__ void hist_k(const int* __restrict__ dstv, int* __restrict__ deg) {
    int e = blockIdx.x * blockDim.x + threadIdx.x;
    if (e < EEDGE) atomicAdd(&deg[dstv[e]], 1);
}

__global__ void scan_k(const int* __restrict__ deg, int* __restrict__ rowptr) {
    __shared__ int part[1024];
    const int CH = (NN + 1023) / 1024;
    int t = threadIdx.x;
    int base = t * CH;
    int s = 0;
    for (int i = 0; i < CH; i++) {
        int idx = base + i;
        if (idx < NN) s += deg[idx];
    }
    part[t] = s;
    __syncthreads();
    for (int off = 1; off < 1024; off <<= 1) {
        int v = (t >= off) ? part[t - off] : 0;
        __syncthreads();
        part[t] += v;
        __syncthreads();
    }
    int run = (t == 0) ? 0 : part[t - 1];
    for (int i = 0; i < CH; i++) {
        int idx = base + i;
        if (idx <= NN) {
            rowptr[idx] = run;
            if (idx < NN) run += deg[idx];
        }
    }
}

__global__ void scatter_k(const int* __restrict__ srcv, const int* __restrict__ dstv,
                          const int* __restrict__ rowptr, int* __restrict__ cursor,
                          int* __restrict__ csrc) {
    int e = blockIdx.x * blockDim.x + threadIdx.x;
    if (e >= EEDGE) return;
    int d = dstv[e];
    int pos = rowptr[d] + atomicAdd(&cursor[d], 1);
    csrc[pos] = srcv[e];
}

// ---------------- GEMMs -------------------------------------------------------

// Layer 1: [N,4] x [4,128]
__global__ void gemm1_k(const float* __restrict__ x, const float* __restrict__ W,
                        float* __restrict__ h) {
    __shared__ float Ws[4 * FF];
    int tid = threadIdx.x;
    if (tid < 4 * FF) Ws[tid] = W[tid];
    __syncthreads();
    int i = blockIdx.x * blockDim.x + tid;
    if (i >= NN * FF) return;
    int n = i >> 7, c = i & 127;
    const float* xr = x + n * 4;
    h[i] = xr[0] * Ws[c] + xr[1] * Ws[FF + c] + xr[2] * Ws[2 * FF + c] + xr[3] * Ws[3 * FF + c];
}

// Layers 2-4: [N,128] x [128,128] via bf16 hi/lo-split tensor-core MMA.
// Block tile 128x128, 8 warps, warp tile 32x64 (2 m-tiles x 8 n-tiles of m16n8k16).
// 3 products: Xhi*Whi + Xhi*Wlo + Xlo*Whi  (error ~2^-16, far under tolerance)
__device__ __forceinline__ void mma_bf16(float* d, const unsigned* a, const unsigned* b) {
    asm volatile(
        "mma.sync.aligned.m16n8k16.row.col.f32.bf16.bf16.f32 "
        "{%0,%1,%2,%3}, {%4,%5,%6,%7}, {%8,%9}, {%0,%1,%2,%3};"
        : "+f"(d[0]), "+f"(d[1]), "+f"(d[2]), "+f"(d[3])
        : "r"(a[0]), "r"(a[1]), "r"(a[2]), "r"(a[3]), "r"(b[0]), "r"(b[1]));
}

__global__ void __launch_bounds__(256, 1)
gemm_tc_k(const float* __restrict__ X, const float* __restrict__ W,
          float* __restrict__ h) {
    extern __shared__ __nv_bfloat16 sm[];
    __nv_bfloat16* Xhi = sm;                   // [128][SX]
    __nv_bfloat16* Xlo = sm + 128 * SX;
    __nv_bfloat16* Whi = sm + 2 * 128 * SX;    // transposed: [n][k]
    __nv_bfloat16* Wlo = sm + 3 * 128 * SX;

    int tid = threadIdx.x;
    int row0 = blockIdx.x * 128;

    // load W transposed + split
    for (int i = tid; i < FF * FF; i += 256) {
        int k = i >> 7, n = i & 127;
        float w = W[i];
        __nv_bfloat16 hi = __float2bfloat16_rn(w);
        __nv_bfloat16 lo = __float2bfloat16_rn(w - __bfloat162float(hi));
        Whi[n * SX + k] = hi;
        Wlo[n * SX + k] = lo;
    }
    // load X tile + split
    for (int i = tid; i < 128 * FF; i += 256) {
        int r = i >> 7, c = i & 127;
        int gr = row0 + r;
        float v = (gr < NN) ? X[(size_t)gr * FF + c] : 0.f;
        __nv_bfloat16 hi = __float2bfloat16_rn(v);
        __nv_bfloat16 lo = __float2bfloat16_rn(v - __bfloat162float(hi));
        Xhi[r * SX + c] = hi;
        Xlo[r * SX + c] = lo;
    }
    __syncthreads();

    int w = tid >> 5;
    int lane = tid & 31;
    int grp = lane >> 2, qd = lane & 3;
    int mr = (w & 3) * 32;       // warp row base within tile
    int nc = (w >> 2) * 64;      // warp col base

    float acc[2][8][4];
#pragma unroll
    for (int mt = 0; mt < 2; mt++)
#pragma unroll
        for (int nt = 0; nt < 8; nt++)
#pragma unroll
            for (int q = 0; q < 4; q++) acc[mt][nt][q] = 0.f;

#pragma unroll 2
    for (int ks = 0; ks < 8; ks++) {
        int k0 = ks * 16;
        unsigned Ah[2][4], Al[2][4];
#pragma unroll
        for (int mt = 0; mt < 2; mt++) {
            int r = mr + mt * 16 + grp;
            int o = r * SX + k0 + qd * 2;
            Ah[mt][0] = *reinterpret_cast<const unsigned*>(&Xhi[o]);
            Ah[mt][1] = *reinterpret_cast<const unsigned*>(&Xhi[o + 8 * SX]);
            Ah[mt][2] = *reinterpret_cast<const unsigned*>(&Xhi[o + 8]);
            Ah[mt][3] = *reinterpret_cast<const unsigned*>(&Xhi[o + 8 * SX + 8]);
            Al[mt][0] = *reinterpret_cast<const unsigned*>(&Xlo[o]);
            Al[mt][1] = *reinterpret_cast<const unsigned*>(&Xlo[o + 8 * SX]);
            Al[mt][2] = *reinterpret_cast<const unsigned*>(&Xlo[o + 8]);
            Al[mt][3] = *reinterpret_cast<const unsigned*>(&Xlo[o + 8 * SX + 8]);
        }
        unsigned Bh[8][2], Bl[8][2];
#pragma unroll
        for (int nt = 0; nt < 8; nt++) {
            int cidx = nc + nt * 8 + grp;
            int o = cidx * SX + k0 + qd * 2;
            Bh[nt][0] = *reinterpret_cast<const unsigned*>(&Whi[o]);
            Bh[nt][1] = *reinterpret_cast<const unsigned*>(&Whi[o + 8]);
            Bl[nt][0] = *reinterpret_cast<const unsigned*>(&Wlo[o]);
            Bl[nt][1] = *reinterpret_cast<const unsigned*>(&Wlo[o + 8]);
        }
#pragma unroll
        for (int mt = 0; mt < 2; mt++)
#pragma unroll
            for (int nt = 0; nt < 8; nt++) {
                mma_bf16(acc[mt][nt], Ah[mt], Bh[nt]);
                mma_bf16(acc[mt][nt], Ah[mt], Bl[nt]);
                mma_bf16(acc[mt][nt], Al[mt], Bh[nt]);
            }
    }

    // epilogue
#pragma unroll
    for (int mt = 0; mt < 2; mt++) {
        int r0 = row0 + mr + mt * 16 + grp;
#pragma unroll
        for (int nt = 0; nt < 8; nt++) {
            int col = nc + nt * 8 + qd * 2;
            if (r0 < NN)
                *reinterpret_cast<float2*>(&h[(size_t)r0 * FF + col]) =
                    make_float2(acc[mt][nt][0], acc[mt][nt][1]);
            if (r0 + 8 < NN)
                *reinterpret_cast<float2*>(&h[(size_t)(r0 + 8) * FF + col]) =
                    make_float2(acc[mt][nt][2], acc[mt][nt][3]);
        }
    }
}

// ---------------- attention ---------------------------------------------------
__global__ void alpha_k(const float* __restrict__ h, const float* __restrict__ asrc,
                        const float* __restrict__ adst,
                        float* __restrict__ as_, float* __restrict__ ad_) {
    int n = (blockIdx.x * blockDim.x + threadIdx.x) >> 5;
    int lane = threadIdx.x & 31;
    if (n >= NN) return;
    const float* hr = h + (size_t)n * FF;
    float v0 = hr[lane],      v1 = hr[lane + 32];
    float v2 = hr[lane + 64], v3 = hr[lane + 96];
    float s0 = v0 * asrc[lane] + v1 * asrc[lane + 32];
    float d0 = v0 * adst[lane] + v1 * adst[lane + 32];
    float s1 = v2 * asrc[64 + lane] + v3 * asrc[96 + lane];
    float d1 = v2 * adst[64 + lane] + v3 * adst[96 + lane];
#pragma unroll
    for (int o = 16; o; o >>= 1) {
        s0 += __shfl_xor_sync(0xffffffffu, s0, o);
        d0 += __shfl_xor_sync(0xffffffffu, d0, o);
        s1 += __shfl_xor_sync(0xffffffffu, s1, o);
        d1 += __shfl_xor_sync(0xffffffffu, d1, o);
    }
    if (lane == 0) {
        as_[n * 2] = s0; as_[n * 2 + 1] = s1;
        ad_[n * 2] = d0; ad_[n * 2 + 1] = d1;
    }
}

// Fused aggregation with ONLINE softmax (single score pass) + gather + bias + ReLU.
__global__ void agg_k(const int* __restrict__ rowptr, const int* __restrict__ csrc,
                      const float* __restrict__ as_, const float* __restrict__ ad_,
                      const float* __restrict__ h, const float* __restrict__ b,
                      float* __restrict__ xo) {
    int n = (blockIdx.x * blockDim.x + threadIdx.x) >> 5;
    int lane = threadIdx.x & 31;
    if (n >= NN) return;
    int beg = rowptr[n], end = rowptr[n + 1];
    float ad0 = ad_[2 * n], ad1 = ad_[2 * n + 1];

    // pass 1: online max+sum (lane-parallel over edges)
    float m0 = -1e30f, s0 = 0.f, m1 = -1e30f, s1 = 0.f;
    for (int i = beg + lane; i < end; i += 32) {
        int s = csrc[i];
        float e0 = as_[2 * s] + ad0;     e0 = e0 > 0.f ? e0 : SLOPE * e0;
        float e1 = as_[2 * s + 1] + ad1; e1 = e1 > 0.f ? e1 : SLOPE * e1;
        float nm0 = fmaxf(m0, e0);
        s0 = s0 * __expf(m0 - nm0) + __expf(e0 - nm0); m0 = nm0;
        float nm1 = fmaxf(m1, e1);
        s1 = s1 * __expf(m1 - nm1) + __expf(e1 - nm1); m1 = nm1;
    }
#pragma unroll
    for (int o = 16; o; o >>= 1) {
        float om = __shfl_xor_sync(0xffffffffu, m0, o);
        float os = __shfl_xor_sync(0xffffffffu, s0, o);
        float nm = fmaxf(m0, om);
        s0 = s0 * __expf(m0 - nm) + os * __expf(om - nm); m0 = nm;
        om = __shfl_xor_sync(0xffffffffu, m1, o);
        os = __shfl_xor_sync(0xffffffffu, s1, o);
        nm = fmaxf(m1, om);
        s1 = s1 * __expf(m1 - nm) + os * __expf(om - nm); m1 = nm;
    }
    float inv0 = 1.f / (s0 + 1e-16f);
    float inv1 = 1.f / (s1 + 1e-16f);

    // pass 2: weighted feature gather (whole warp per edge)
    float4 acc = make_float4(0.f, 0.f, 0.f, 0.f);
    for (int i = beg; i < end; i++) {
        int s = csrc[i];
        float e0 = as_[2 * s] + ad0;     e0 = e0 > 0.f ? e0 : SLOPE * e0;
        float e1 = as_[2 * s + 1] + ad1; e1 = e1 > 0.f ? e1 : SLOPE * e1;
        float p = (lane < 16) ? __expf(e0 - m0) * inv0 : __expf(e1 - m1) * inv1;
        float4 v = reinterpret_cast<const float4*>(h + (size_t)s * FF)[lane];
        acc.x += v.x * p; acc.y += v.y * p; acc.z += v.z * p; acc.w += v.w * p;
    }

    float4 bv = reinterpret_cast<const float4*>(b)[lane];
    float4 r;
    r.x = fmaxf(acc.x + bv.x, 0.f);
    r.y = fmaxf(acc.y + bv.y, 0.f);
    r.z = fmaxf(acc.z + bv.z, 0.f);
    r.w = fmaxf(acc.w + bv.w, 0.f);
    reinterpret_cast<float4*>(xo + (size_t)n * FF)[lane] = r;
}

// ---------------- pooling + classifier ----------------------------------------
__global__ void poolinit_k(float* __restrict__ pooled, float* __restrict__ cnt) {
    int i = blockIdx.x * blockDim.x + threadIdx.x;
    if (i < GG * FF) pooled[i] = 0.f;
    if (i < GG) cnt[i] = 0.f;
}

// batch is sorted: block of 128 threads (one column each) runs over 128 nodes,
// emitting atomics only at graph boundaries.
#define PB 128
__global__ void pool_k(const int* __restrict__ batch, const float* __restrict__ x,
                       float* __restrict__ pooled, float* __restrict__ cnt) {
    int c = threadIdx.x;
    int n0 = blockIdx.x * PB;
    int nend = min(n0 + PB, NN);
    if (n0 >= NN) return;
    int curg = batch[n0];
    float run = 0.f;
    for (int n = n0; n < nend; n++) {
        int g = batch[n];
        if (g != curg) {
            atomicAdd(&pooled[curg * FF + c], run);
            run = 0.f; curg = g;
        }
        run += x[(size_t)n * FF + c];
    }
    atomicAdd(&pooled[curg * FF + c], run);
    if (c == 0) {
        int cg = batch[n0]; float cr = 0.f;
        for (int n = n0; n < nend; n++) {
            int g = batch[n];
            if (g != cg) { atomicAdd(&cnt[cg], cr); cr = 0.f; cg = g; }
            cr += 1.f;
        }
        atomicAdd(&cnt[cg], cr);
    }
}

__global__ void final_k(const float* __restrict__ pooled, const float* __restrict__ cnt,
                        const float* __restrict__ lw, const float* __restrict__ lb,
                        float* __restrict__ out) {
    int t = threadIdx.x;
    if (t >= GG * CC) return;
    int g = t / CC, c = t % CC;
    float inv = 1.f / fmaxf(cnt[g], 1.f);
    float acc = lb[c];
    for (int k = 0; k < FF; k++)
        acc += pooled[g * FF + k] * inv * lw[k * CC + c];
    out[t] = 1.f / (1.f + expf(-acc));
}

// ---------------- launch ------------------------------------------------------
extern "C" void kernel_launch(void* const* d_in, const int* in_sizes, int n_in,
                              void* d_out, int out_size) {
    const float* x     = (const float*)d_in[0];
    const int*   ei    = (const int*)d_in[1];
    const int*   batch = (const int*)d_in[2];
    const float* W[4]    = {(const float*)d_in[3],  (const float*)d_in[7],
                            (const float*)d_in[11], (const float*)d_in[15]};
    const float* asrc[4] = {(const float*)d_in[4],  (const float*)d_in[8],
                            (const float*)d_in[12], (const float*)d_in[16]};
    const float* adst[4] = {(const float*)d_in[5],  (const float*)d_in[9],
                            (const float*)d_in[13], (const float*)d_in[17]};
    const float* bias[4] = {(const float*)d_in[6],  (const float*)d_in[10],
                            (const float*)d_in[14], (const float*)d_in[18]};
    const float* lin_w = (const float*)d_in[19];
    const float* lin_b = (const float*)d_in[20];
    float* out = (float*)d_out;

    const int* srcv = ei;
    const int* dstv = ei + EEDGE;

    void *ph, *px, *pas, *pad, *ppool, *pcnt, *pdeg, *pcur, *prp, *pcs;
    cudaGetSymbolAddress(&ph,   g_h);
    cudaGetSymbolAddress(&px,   g_x);
    cudaGetSymbolAddress(&pas,  g_as);
    cudaGetSymbolAddress(&pad,  g_ad);
    cudaGetSymbolAddress(&ppool,g_pool);
    cudaGetSymbolAddress(&pcnt, g_cnt);
    cudaGetSymbolAddress(&pdeg, g_deg);
    cudaGetSymbolAddress(&pcur, g_cursor);
    cudaGetSymbolAddress(&prp,  g_rowptr);
    cudaGetSymbolAddress(&pcs,  g_csrc);

    const int SMEM_TC = 4 * 128 * SX * (int)sizeof(__nv_bfloat16);   // 135168 B
    cudaFuncSetAttribute(gemm_tc_k, cudaFuncAttributeMaxDynamicSharedMemorySize, SMEM_TC);

    const int NF = NN * FF;

    // ---- CSR build (shared by all 4 layers) ----
    zero_k<<<(NN + 255) / 256, 256>>>((int*)pdeg, (int*)pcur);
    hist_k<<<(EEDGE + 255) / 256, 256>>>(dstv, (int*)pdeg);
    scan_k<<<1, 1024>>>((const int*)pdeg, (int*)prp);
    scatter_k<<<(EEDGE + 255) / 256, 256>>>(srcv, dstv, (const int*)prp,
                                            (int*)pcur, (int*)pcs);

    // ---- 4 GAT layers ----
    for (int l = 0; l < 4; l++) {
        if (l == 0) {
            gemm1_k<<<(NF + 511) / 512, 512>>>(x, W[0], (float*)ph);
        } else {
            gemm_tc_k<<<(NN + 127) / 128, 256, SMEM_TC>>>((const float*)px, W[l], (float*)ph);
        }
        alpha_k<<<(NN + 7) / 8, 256>>>((const float*)ph, asrc[l], adst[l],
                                       (float*)pas, (float*)pad);
        agg_k<<<(NN * 32 + 255) / 256, 256>>>((const int*)prp, (const int*)pcs,
                                              (const float*)pas, (const float*)pad,
                                              (const float*)ph, bias[l], (float*)px);
    }

    // ---- pooling + classifier ----
    poolinit_k<<<(GG * FF + 255) / 256, 256>>>((float*)ppool, (float*)pcnt);
    pool_k<<<(NN + PB - 1) / PB, PB>>>(batch, (const float*)px,
                                       (float*)ppool, (float*)pcnt);
    final_k<<<1, 512>>>((const float*)ppool, (const float*)pcnt, lin_w, lin_b, out);
}

// round 8
// speedup vs baseline: 3.2472x; 1.0762x over previous
#include <cuda_runtime.h>
#include <cuda_bf16.h>

#define NN 50000
#define EEDGE 500000
#define GG 64
#define HH 2
#define FF 128          // H*D
#define CC 5
#define SLOPE 0.2f
#define SX 132          // padded bf16 row stride

// ---------------- scratch (device globals) ------------------------------------
__device__ float g_h[NN * FF];
__device__ float g_x[NN * FF];
__device__ float g_as[NN * HH];
__device__ float g_ad[NN * HH];
__device__ float g_pool[GG * FF];
__device__ float g_cnt[GG];
__device__ int   g_deg[NN];
__device__ int   g_cursor[NN];
__device__ int   g_rowptr[NN + 1];
__device__ int   g_csrc[EEDGE];

// ---------------- setup + CSR build -------------------------------------------
__global__ void setup_k(int* __restrict__ deg, int* __restrict__ cursor,
                        float* __restrict__ pooled, float* __restrict__ cnt) {
    int i = blockIdx.x * blockDim.x + threadIdx.x;
    if (i < NN) { deg[i] = 0; cursor[i] = 0; }
    if (i < GG * FF) pooled[i] = 0.f;
    if (i < GG) cnt[i] = 0.f;
}

__global__ void hist_k(const int* __restrict__ dstv, int* __restrict__ deg) {
    int e = blockIdx.x * blockDim.x + threadIdx.x;
    if (e < EEDGE) atomicAdd(&deg[dstv[e]], 1);
}

__global__ void scan_k(const int* __restrict__ deg, int* __restrict__ rowptr) {
    __shared__ int part[1024];
    const int CH = (NN + 1023) / 1024;
    int t = threadIdx.x;
    int base = t * CH;
    int s = 0;
    for (int i = 0; i < CH; i++) {
        int idx = base + i;
        if (idx < NN) s += deg[idx];
    }
    part[t] = s;
    __syncthreads();
    for (int off = 1; off < 1024; off <<= 1) {
        int v = (t >= off) ? part[t - off] : 0;
        __syncthreads();
        part[t] += v;
        __syncthreads();
    }
    int run = (t == 0) ? 0 : part[t - 1];
    for (int i = 0; i < CH; i++) {
        int idx = base + i;
        if (idx <= NN) {
            rowptr[idx] = run;
            if (idx < NN) run += deg[idx];
        }
    }
}

__global__ void scatter_k(const int* __restrict__ srcv, const int* __restrict__ dstv,
                          const int* __restrict__ rowptr, int* __restrict__ cursor,
                          int* __restrict__ csrc) {
    int e = blockIdx.x * blockDim.x + threadIdx.x;
    if (e >= EEDGE) return;
    int d = dstv[e];
    int pos = rowptr[d] + atomicAdd(&cursor[d], 1);
    csrc[pos] = srcv[e];
}

// ---------------- GEMMs -------------------------------------------------------

// Layer 1: [N,4] x [4,128]
__global__ void gemm1_k(const float* __restrict__ x, const float* __restrict__ W,
                        float* __restrict__ h) {
    __shared__ float Ws[4 * FF];
    int tid = threadIdx.x;
    if (tid < 4 * FF) Ws[tid] = W[tid];
    __syncthreads();
    int i = blockIdx.x * blockDim.x + tid;
    if (i >= NN * FF) return;
    int n = i >> 7, c = i & 127;
    const float* xr = x + n * 4;
    h[i] = xr[0] * Ws[c] + xr[1] * Ws[FF + c] + xr[2] * Ws[2 * FF + c] + xr[3] * Ws[3 * FF + c];
}

// Per-node attention coefficients (used after layer-1 GEMM only)
__global__ void alpha_k(const float* __restrict__ h, const float* __restrict__ asrc,
                        const float* __restrict__ adst,
                        float* __restrict__ as_, float* __restrict__ ad_) {
    int n = (blockIdx.x * blockDim.x + threadIdx.x) >> 5;
    int lane = threadIdx.x & 31;
    if (n >= NN) return;
    const float* hr = h + (size_t)n * FF;
    float v0 = hr[lane],      v1 = hr[lane + 32];
    float v2 = hr[lane + 64], v3 = hr[lane + 96];
    float s0 = v0 * asrc[lane] + v1 * asrc[lane + 32];
    float d0 = v0 * adst[lane] + v1 * adst[lane + 32];
    float s1 = v2 * asrc[64 + lane] + v3 * asrc[96 + lane];
    float d1 = v2 * adst[64 + lane] + v3 * adst[96 + lane];
#pragma unroll
    for (int o = 16; o; o >>= 1) {
        s0 += __shfl_xor_sync(0xffffffffu, s0, o);
        d0 += __shfl_xor_sync(0xffffffffu, d0, o);
        s1 += __shfl_xor_sync(0xffffffffu, s1, o);
        d1 += __shfl_xor_sync(0xffffffffu, d1, o);
    }
    if (lane == 0) {
        as_[n * 2] = s0; as_[n * 2 + 1] = s1;
        ad_[n * 2] = d0; ad_[n * 2 + 1] = d1;
    }
}

// Layers 2-4: bf16 hi/lo split tensor-core GEMM, alpha fused into epilogue.
__device__ __forceinline__ void mma_bf16(float* d, const unsigned* a, const unsigned* b) {
    asm volatile(
        "mma.sync.aligned.m16n8k16.row.col.f32.bf16.bf16.f32 "
        "{%0,%1,%2,%3}, {%4,%5,%6,%7}, {%8,%9}, {%0,%1,%2,%3};"
        : "+f"(d[0]), "+f"(d[1]), "+f"(d[2]), "+f"(d[3])
        : "r"(a[0]), "r"(a[1]), "r"(a[2]), "r"(a[3]), "r"(b[0]), "r"(b[1]));
}

__global__ void __launch_bounds__(256, 1)
gemm_tc_k(const float* __restrict__ X, const float* __restrict__ W,
          const float* __restrict__ asrc, const float* __restrict__ adst,
          float* __restrict__ h, float* __restrict__ as_, float* __restrict__ ad_) {
    extern __shared__ __nv_bfloat16 sm[];
    __nv_bfloat16* Xhi = sm;                   // [128][SX]
    __nv_bfloat16* Xlo = sm + 128 * SX;
    __nv_bfloat16* Whi = sm + 2 * 128 * SX;    // transposed [n][k]
    __nv_bfloat16* Wlo = sm + 3 * 128 * SX;

    int tid = threadIdx.x;
    int row0 = blockIdx.x * 128;

    for (int i = tid; i < FF * FF; i += 256) {
        int k = i >> 7, n = i & 127;
        float w = W[i];
        __nv_bfloat16 hi = __float2bfloat16_rn(w);
        __nv_bfloat16 lo = __float2bfloat16_rn(w - __bfloat162float(hi));
        Whi[n * SX + k] = hi;
        Wlo[n * SX + k] = lo;
    }
    for (int i = tid; i < 128 * FF; i += 256) {
        int r = i >> 7, c = i & 127;
        int gr = row0 + r;
        float v = (gr < NN) ? X[(size_t)gr * FF + c] : 0.f;
        __nv_bfloat16 hi = __float2bfloat16_rn(v);
        __nv_bfloat16 lo = __float2bfloat16_rn(v - __bfloat162float(hi));
        Xhi[r * SX + c] = hi;
        Xlo[r * SX + c] = lo;
    }
    __syncthreads();

    int w = tid >> 5;
    int lane = tid & 31;
    int grp = lane >> 2, qd = lane & 3;
    int mr = (w & 3) * 32;
    int nc = (w >> 2) * 64;      // 0 -> head 0, 64 -> head 1
    int head = nc >> 6;

    float acc[2][8][4];
#pragma unroll
    for (int mt = 0; mt < 2; mt++)
#pragma unroll
        for (int nt = 0; nt < 8; nt++)
#pragma unroll
            for (int q = 0; q < 4; q++) acc[mt][nt][q] = 0.f;

#pragma unroll 2
    for (int ks = 0; ks < 8; ks++) {
        int k0 = ks * 16;
        unsigned Ah[2][4], Al[2][4];
#pragma unroll
        for (int mt = 0; mt < 2; mt++) {
            int r = mr + mt * 16 + grp;
            int o = r * SX + k0 + qd * 2;
            Ah[mt][0] = *reinterpret_cast<const unsigned*>(&Xhi[o]);
            Ah[mt][1] = *reinterpret_cast<const unsigned*>(&Xhi[o + 8 * SX]);
            Ah[mt][2] = *reinterpret_cast<const unsigned*>(&Xhi[o + 8]);
            Ah[mt][3] = *reinterpret_cast<const unsigned*>(&Xhi[o + 8 * SX + 8]);
            Al[mt][0] = *reinterpret_cast<const unsigned*>(&Xlo[o]);
            Al[mt][1] = *reinterpret_cast<const unsigned*>(&Xlo[o + 8 * SX]);
            Al[mt][2] = *reinterpret_cast<const unsigned*>(&Xlo[o + 8]);
            Al[mt][3] = *reinterpret_cast<const unsigned*>(&Xlo[o + 8 * SX + 8]);
        }
        unsigned Bh[8][2], Bl[8][2];
#pragma unroll
        for (int nt = 0; nt < 8; nt++) {
            int cidx = nc + nt * 8 + grp;
            int o = cidx * SX + k0 + qd * 2;
            Bh[nt][0] = *reinterpret_cast<const unsigned*>(&Whi[o]);
            Bh[nt][1] = *reinterpret_cast<const unsigned*>(&Whi[o + 8]);
            Bl[nt][0] = *reinterpret_cast<const unsigned*>(&Wlo[o]);
            Bl[nt][1] = *reinterpret_cast<const unsigned*>(&Wlo[o + 8]);
        }
#pragma unroll
        for (int mt = 0; mt < 2; mt++)
#pragma unroll
            for (int nt = 0; nt < 8; nt++) {
                mma_bf16(acc[mt][nt], Ah[mt], Bh[nt]);
                mma_bf16(acc[mt][nt], Ah[mt], Bl[nt]);
                mma_bf16(acc[mt][nt], Al[mt], Bh[nt]);
            }
    }

    // load alpha vectors for this warp's 16 columns
    float av[8][2], dv[8][2];
#pragma unroll
    for (int nt = 0; nt < 8; nt++)
#pragma unroll
        for (int c = 0; c < 2; c++) {
            int col = head * 64 + nt * 8 + qd * 2 + c;
            av[nt][c] = asrc[col];
            dv[nt][c] = adst[col];
        }

    // epilogue: write h + fused alpha reduction
#pragma unroll
    for (int mt = 0; mt < 2; mt++) {
        int r0 = row0 + mr + mt * 16 + grp;
        float sa = 0.f, sd = 0.f, sa2 = 0.f, sd2 = 0.f;
#pragma unroll
        for (int nt = 0; nt < 8; nt++) {
            int col = nc + nt * 8 + qd * 2;
            if (r0 < NN)
                *reinterpret_cast<float2*>(&h[(size_t)r0 * FF + col]) =
                    make_float2(acc[mt][nt][0], acc[mt][nt][1]);
            if (r0 + 8 < NN)
                *reinterpret_cast<float2*>(&h[(size_t)(r0 + 8) * FF + col]) =
                    make_float2(acc[mt][nt][2], acc[mt][nt][3]);
#pragma unroll
            for (int c = 0; c < 2; c++) {
                sa  += acc[mt][nt][c]     * av[nt][c];
                sd  += acc[mt][nt][c]     * dv[nt][c];
                sa2 += acc[mt][nt][2 + c] * av[nt][c];
                sd2 += acc[mt][nt][2 + c] * dv[nt][c];
            }
        }
#pragma unroll
        for (int o = 1; o <= 2; o <<= 1) {
            sa  += __shfl_xor_sync(0xffffffffu, sa,  o);
            sd  += __shfl_xor_sync(0xffffffffu, sd,  o);
            sa2 += __shfl_xor_sync(0xffffffffu, sa2, o);
            sd2 += __shfl_xor_sync(0xffffffffu, sd2, o);
        }
        if (qd == 0) {
            if (r0 < NN)     { as_[2 * r0 + head] = sa;       ad_[2 * r0 + head] = sd; }
            if (r0 + 8 < NN) { as_[2 * (r0 + 8) + head] = sa2; ad_[2 * (r0 + 8) + head] = sd2; }
        }
    }
}

// ---------------- fused aggregation -------------------------------------------
// Warp per node. Fast path (deg<=32): indices/weights register-resident,
// gather unrolled x4 via shuffle broadcast.
__global__ void agg_k(const int* __restrict__ rowptr, const int* __restrict__ csrc,
                      const float* __restrict__ as_, const float* __restrict__ ad_,
                      const float* __restrict__ h, const float* __restrict__ b,
                      float* __restrict__ xo) {
    int n = (blockIdx.x * blockDim.x + threadIdx.x) >> 5;
    int lane = threadIdx.x & 31;
    if (n >= NN) return;
    int beg = rowptr[n], end = rowptr[n + 1];
    int deg = end - beg;
    float ad0 = ad_[2 * n], ad1 = ad_[2 * n + 1];

    float4 acc = make_float4(0.f, 0.f, 0.f, 0.f);

    if (deg <= 32) {
        int sreg = 0;
        float e0 = -1e30f, e1 = -1e30f;
        if (lane < deg) {
            sreg = csrc[beg + lane];
            e0 = as_[2 * sreg] + ad0;     e0 = e0 > 0.f ? e0 : SLOPE * e0;
            e1 = as_[2 * sreg + 1] + ad1; e1 = e1 > 0.f ? e1 : SLOPE * e1;
        }
        float m0 = e0, m1 = e1;
#pragma unroll
        for (int o = 16; o; o >>= 1) {
            m0 = fmaxf(m0, __shfl_xor_sync(0xffffffffu, m0, o));
            m1 = fmaxf(m1, __shfl_xor_sync(0xffffffffu, m1, o));
        }
        float p0 = (lane < deg) ? __expf(e0 - m0) : 0.f;
        float p1 = (lane < deg) ? __expf(e1 - m1) : 0.f;
        float s0 = p0, s1 = p1;
#pragma unroll
        for (int o = 16; o; o >>= 1) {
            s0 += __shfl_xor_sync(0xffffffffu, s0, o);
            s1 += __shfl_xor_sync(0xffffffffu, s1, o);
        }
        float pr0 = p0 / (s0 + 1e-16f);
        float pr1 = p1 / (s1 + 1e-16f);

        int j = 0;
        for (; j + 4 <= deg; j += 4) {
            int i0 = __shfl_sync(0xffffffffu, sreg, j);
            int i1 = __shfl_sync(0xffffffffu, sreg, j + 1);
            int i2 = __shfl_sync(0xffffffffu, sreg, j + 2);
            int i3 = __shfl_sync(0xffffffffu, sreg, j + 3);
            float a0 = __shfl_sync(0xffffffffu, pr0, j);
            float b0 = __shfl_sync(0xffffffffu, pr1, j);
            float a1 = __shfl_sync(0xffffffffu, pr0, j + 1);
            float b1 = __shfl_sync(0xffffffffu, pr1, j + 1);
            float a2 = __shfl_sync(0xffffffffu, pr0, j + 2);
            float b2 = __shfl_sync(0xffffffffu, pr1, j + 2);
            float a3 = __shfl_sync(0xffffffffu, pr0, j + 3);
            float b3 = __shfl_sync(0xffffffffu, pr1, j + 3);
            float4 v0 = reinterpret_cast<const float4*>(h + (size_t)i0 * FF)[lane];
            float4 v1 = reinterpret_cast<const float4*>(h + (size_t)i1 * FF)[lane];
            float4 v2 = reinterpret_cast<const float4*>(h + (size_t)i2 * FF)[lane];
            float4 v3 = reinterpret_cast<const float4*>(h + (size_t)i3 * FF)[lane];
            float w0 = lane < 16 ? a0 : b0;
            float w1 = lane < 16 ? a1 : b1;
            float w2 = lane < 16 ? a2 : b2;
            float w3 = lane < 16 ? a3 : b3;
            acc.x += v0.x * w0 + v1.x * w1 + v2.x * w2 + v3.x * w3;
            acc.y += v0.y * w0 + v1.y * w1 + v2.y * w2 + v3.y * w3;
            acc.z += v0.z * w0 + v1.z * w1 + v2.z * w2 + v3.z * w3;
            acc.w += v0.w * w0 + v1.w * w1 + v2.w * w2 + v3.w * w3;
        }
        for (; j < deg; j++) {
            int i0 = __shfl_sync(0xffffffffu, sreg, j);
            float a0 = __shfl_sync(0xffffffffu, pr0, j);
            float b0 = __shfl_sync(0xffffffffu, pr1, j);
            float w0 = lane < 16 ? a0 : b0;
            float4 v0 = reinterpret_cast<const float4*>(h + (size_t)i0 * FF)[lane];
            acc.x += v0.x * w0; acc.y += v0.y * w0;
            acc.z += v0.z * w0; acc.w += v0.w * w0;
        }
    } else {
        // fallback: online softmax + sequential gather
        float m0 = -1e30f, s0 = 0.f, m1 = -1e30f, s1 = 0.f;
        for (int i = beg + lane; i < end; i += 32) {
            int s = csrc[i];
            float e0 = as_[2 * s] + ad0;     e0 = e0 > 0.f ? e0 : SLOPE * e0;
            float e1 = as_[2 * s + 1] + ad1; e1 = e1 > 0.f ? e1 : SLOPE * e1;
            float nm0 = fmaxf(m0, e0);
            s0 = s0 * __expf(m0 - nm0) + __expf(e0 - nm0); m0 = nm0;
            float nm1 = fmaxf(m1, e1);
            s1 = s1 * __expf(m1 - nm1) + __expf(e1 - nm1); m1 = nm1;
        }
#pragma unroll
        for (int o = 16; o; o >>= 1) {
            float om = __shfl_xor_sync(0xffffffffu, m0, o);
            float os = __shfl_xor_sync(0xffffffffu, s0, o);
            float nm = fmaxf(m0, om);
            s0 = s0 * __expf(m0 - nm) + os * __expf(om - nm); m0 = nm;
            om = __shfl_xor_sync(0xffffffffu, m1, o);
            os = __shfl_xor_sync(0xffffffffu, s1, o);
            nm = fmaxf(m1, om);
            s1 = s1 * __expf(m1 - nm) + os * __expf(om - nm); m1 = nm;
        }
        float inv0 = 1.f / (s0 + 1e-16f);
        float inv1 = 1.f / (s1 + 1e-16f);
        for (int i = beg; i < end; i++) {
            int s = csrc[i];
            float e0 = as_[2 * s] + ad0;     e0 = e0 > 0.f ? e0 : SLOPE * e0;
            float e1 = as_[2 * s + 1] + ad1; e1 = e1 > 0.f ? e1 : SLOPE * e1;
            float p = (lane < 16) ? __expf(e0 - m0) * inv0 : __expf(e1 - m1) * inv1;
            float4 v = reinterpret_cast<const float4*>(h + (size_t)s * FF)[lane];
            acc.x += v.x * p; acc.y += v.y * p; acc.z += v.z * p; acc.w += v.w * p;
        }
    }

    float4 bv = reinterpret_cast<const float4*>(b)[lane];
    float4 r;
    r.x = fmaxf(acc.x + bv.x, 0.f);
    r.y = fmaxf(acc.y + bv.y, 0.f);
    r.z = fmaxf(acc.z + bv.z, 0.f);
    r.w = fmaxf(acc.w + bv.w, 0.f);
    reinterpret_cast<float4*>(xo + (size_t)n * FF)[lane] = r;
}

// ---------------- pooling + classifier ----------------------------------------
#define PB 128
__global__ void pool_k(const int* __restrict__ batch, const float* __restrict__ x,
                       float* __restrict__ pooled, float* __restrict__ cnt) {
    int c = threadIdx.x;
    int n0 = blockIdx.x * PB;
    int nend = min(n0 + PB, NN);
    if (n0 >= NN) return;
    int curg = batch[n0];
    float run = 0.f;
    for (int n = n0; n < nend; n++) {
        int g = batch[n];
        if (g != curg) {
            atomicAdd(&pooled[curg * FF + c], run);
            run = 0.f; curg = g;
        }
        run += x[(size_t)n * FF + c];
    }
    atomicAdd(&pooled[curg * FF + c], run);
    if (c == 0) {
        int cg = batch[n0]; float cr = 0.f;
        for (int n = n0; n < nend; n++) {
            int g = batch[n];
            if (g != cg) { atomicAdd(&cnt[cg], cr); cr = 0.f; cg = g; }
            cr += 1.f;
        }
        atomicAdd(&cnt[cg], cr);
    }
}

__global__ void final_k(const float* __restrict__ pooled, const float* __restrict__ cnt,
                        const float* __restrict__ lw, const float* __restrict__ lb,
                        float* __restrict__ out) {
    int t = threadIdx.x;
    if (t >= GG * CC) return;
    int g = t / CC, c = t % CC;
    float inv = 1.f / fmaxf(cnt[g], 1.f);
    float acc = lb[c];
    for (int k = 0; k < FF; k++)
        acc += pooled[g * FF + k] * inv * lw[k * CC + c];
    out[t] = 1.f / (1.f + expf(-acc));
}

// ---------------- launch ------------------------------------------------------
extern "C" void kernel_launch(void* const* d_in, const int* in_sizes, int n_in,
                              void* d_out, int out_size) {
    const float* x     = (const float*)d_in[0];
    const int*   ei    = (const int*)d_in[1];
    const int*   batch = (const int*)d_in[2];
    const float* W[4]    = {(const float*)d_in[3],  (const float*)d_in[7],
                            (const float*)d_in[11], (const float*)d_in[15]};
    const float* asrc[4] = {(const float*)d_in[4],  (const float*)d_in[8],
                            (const float*)d_in[12], (const float*)d_in[16]};
    const float* adst[4] = {(const float*)d_in[5],  (const float*)d_in[9],
                            (const float*)d_in[13], (const float*)d_in[17]};
    const float* bias[4] = {(const float*)d_in[6],  (const float*)d_in[10],
                            (const float*)d_in[14], (const float*)d_in[18]};
    const float* lin_w = (const float*)d_in[19];
    const float* lin_b = (const float*)d_in[20];
    float* out = (float*)d_out;

    const int* srcv = ei;
    const int* dstv = ei + EEDGE;

    void *ph, *px, *pas, *pad, *ppool, *pcnt, *pdeg, *pcur, *prp, *pcs;
    cudaGetSymbolAddress(&ph,   g_h);
    cudaGetSymbolAddress(&px,   g_x);
    cudaGetSymbolAddress(&pas,  g_as);
    cudaGetSymbolAddress(&pad,  g_ad);
    cudaGetSymbolAddress(&ppool,g_pool);
    cudaGetSymbolAddress(&pcnt, g_cnt);
    cudaGetSymbolAddress(&pdeg, g_deg);
    cudaGetSymbolAddress(&pcur, g_cursor);
    cudaGetSymbolAddress(&prp,  g_rowptr);
    cudaGetSymbolAddress(&pcs,  g_csrc);

    const int SMEM_TC = 4 * 128 * SX * (int)sizeof(__nv_bfloat16);   // 135168 B
    cudaFuncSetAttribute(gemm_tc_k, cudaFuncAttributeMaxDynamicSharedMemorySize, SMEM_TC);

    const int NF = NN * FF;

    // ---- setup + CSR build ----
    setup_k<<<(NN + 255) / 256, 256>>>((int*)pdeg, (int*)pcur, (float*)ppool, (float*)pcnt);
    hist_k<<<(EEDGE + 255) / 256, 256>>>(dstv, (int*)pdeg);
    scan_k<<<1, 1024>>>((const int*)pdeg, (int*)prp);
    scatter_k<<<(EEDGE + 255) / 256, 256>>>(srcv, dstv, (const int*)prp,
                                            (int*)pcur, (int*)pcs);

    // ---- 4 GAT layers ----
    for (int l = 0; l < 4; l++) {
        if (l == 0) {
            gemm1_k<<<(NF + 511) / 512, 512>>>(x, W[0], (float*)ph);
            alpha_k<<<(NN + 7) / 8, 256>>>((const float*)ph, asrc[0], adst[0],
                                           (float*)pas, (float*)pad);
        } else {
            gemm_tc_k<<<(NN + 127) / 128, 256, SMEM_TC>>>((const float*)px, W[l],
                                                          asrc[l], adst[l],
                                                          (float*)ph, (float*)pas, (float*)pad);
        }
        agg_k<<<(NN * 32 + 255) / 256, 256>>>((const int*)prp, (const int*)pcs,
                                              (const float*)pas, (const float*)pad,
                                              (const float*)ph, bias[l], (float*)px);
    }

    // ---- pooling + classifier ----
    pool_k<<<(NN + PB - 1) / PB, PB>>>(batch, (const float*)px,
                                       (float*)ppool, (float*)pcnt);
    final_k<<<1, 512>>>((const float*)ppool, (const float*)pcnt, lin_w, lin_b, out);
}